// round 12
// baseline (speedup 1.0000x reference)
#include <cuda_runtime.h>
#include <cstdint>

// EfficientInteractionBilinear — fused mma.sync (tf32), K32 chunks, reg-B.
// out[n,u] = sum_{i,e} A[n,i,e] * W[e,i,u]
//   S[n,s,e] = sum_k sph[n,s,k]*m2[n,k,e]      (s_gen -> g_S scratch)
//   A[n,c]   = sum_s rbf[n,i,s]*S[n,s,e]       (producer warps, fp32)
//   out      = A @ Wk^T via mma.sync m16n8k8 tf32 (consumer warps)
// K = 4096 = 128 chunks of 32 (chunk q: eb=q>>4 -> 8-e block, p2=q&15 ->
// i-quad; in-chunk k = il*8 + e_local, mma k-slice ks = il).
// Consumers read B-fragments directly from L2-hot g_W into registers
// (prefetch next chunk during current mma) — B never touches smem.

#define NSPH   16
#define KMAXC  16
#define EMB    64
#define INTERM 64
#define UOUT   128
#define MAXE   50176

// ---------------- device scratch (allocations forbidden) ----------------
__device__ int      g_tri[MAXE * KMAXC];
__device__ int      g_idx64;
__device__ float    g_S[(size_t)MAXE * 1024];   // [n][s16][e64]
__device__ unsigned g_W[(size_t)128 * 4096];    // per K32 chunk: B-frag order 16KB

// ---------------- helpers ----------------
__device__ __forceinline__ unsigned cvt_tf32(float f) {
    unsigned r; asm("cvt.rn.tf32.f32 %0, %1;" : "=r"(r) : "f"(f)); return r;
}
__device__ __forceinline__ void cp16(void* smem_dst, const void* gmem_src) {
    unsigned a = (unsigned)__cvta_generic_to_shared(smem_dst);
    asm volatile("cp.async.cg.shared.global [%0], [%1], 16;" :: "r"(a), "l"(gmem_src));
}
#define CP_COMMIT() asm volatile("cp.async.commit_group;" ::: "memory")
#define CP_WAIT(n)  asm volatile("cp.async.wait_group %0;" :: "n"(n) : "memory")

#define MMA(c, a, b) asm volatile( \
    "mma.sync.aligned.m16n8k8.row.col.f32.tf32.tf32.f32 " \
    "{%0,%1,%2,%3}, {%4,%5,%6,%7}, {%8,%9}, {%0,%1,%2,%3};" \
    : "+f"((c)[0]), "+f"((c)[1]), "+f"((c)[2]), "+f"((c)[3]) \
    : "r"((a).x), "r"((a).y), "r"((a).z), "r"((a).w), "r"((b).x), "r"((b).y))

// ---------------- prologue (validated) ----------------
__global__ void detect_idx_dtype(const int* __restrict__ kw, int nt)
{
    if (blockIdx.x == 0 && threadIdx.x == 0) {
        int n = nt < 128 ? nt : 128, f = 1;
        for (int t = 0; t < n; ++t) if (kw[2*t+1] != 0) { f = 0; break; }
        g_idx64 = f;
    }
}
__global__ void init_map(int ne)
{
    int i = blockIdx.x * blockDim.x + threadIdx.x;
    if (i < ne * KMAXC) g_tri[i] = -1;
}
__global__ void scatter_map(const void* idr, const void* kid, int nt, int ne)
{
    int t = blockIdx.x * blockDim.x + threadIdx.x;
    if (t >= nt) return;
    long long e, k;
    if (g_idx64) { e = ((const long long*)idr)[t]; k = ((const long long*)kid)[t]; }
    else         { e = ((const int*)idr)[t];       k = ((const int*)kid)[t]; }
    if (e >= 0 && e < ne && k >= 0 && k < KMAXC) g_tri[(int)e*KMAXC + (int)k] = t;
}

// ---------------- S = sph @ m2, one warp per edge (validated) ----------------
__global__ __launch_bounds__(256) void s_gen(const float* __restrict__ sph,
                                             const float* __restrict__ m, int ne)
{
    __shared__ float sphs[8][256];
    int w = threadIdx.x >> 5, l = threadIdx.x & 31;
    int n = blockIdx.x * 8 + w;
    if (n >= ne) return;
    for (int j = l; j < 256; j += 32) sphs[w][j] = sph[(size_t)n*256 + j];
    int tmine = (l < KMAXC) ? g_tri[n*KMAXC + l] : -1;
    __syncwarp();
    float a0[16], a1[16];
    #pragma unroll
    for (int s = 0; s < 16; ++s) { a0[s] = 0.f; a1[s] = 0.f; }
    for (int k = 0; k < 16; ++k) {
        int t = __shfl_sync(0xFFFFFFFFu, tmine, k);
        float m0 = 0.f, m1 = 0.f;
        if (t >= 0) {
            float2 mv = *(const float2*)&m[(size_t)t*EMB + 2*l];
            m0 = mv.x; m1 = mv.y;
        }
        #pragma unroll
        for (int s = 0; s < 16; ++s) {
            float c = sphs[w][s*16 + k];
            a0[s] += c * m0; a1[s] += c * m1;
        }
    }
    #pragma unroll
    for (int s = 0; s < 16; ++s)
        *(float2*)&g_S[(size_t)n*1024 + s*64 + 2*l] = make_float2(a0[s], a1[s]);
}

// ---------------- W -> tf32 in B-fragment order, K32 chunks ----------------
// chunk q (128): image [j 16][ks 4][lane 32][2 u32] = 16KB
// ks = i_local; b0 = Wk[u=j*8+(lane>>2)][e=eb*8+(lane&3), i=p2*4+ks], b1: e+4
__global__ void wstage(const float* __restrict__ wgt)
{
    int gid = blockIdx.x*256 + threadIdx.x;           // 262144 total
    int lane = gid & 31, ks = (gid >> 5) & 3, j = (gid >> 7) & 15, q = gid >> 11;
    int g8 = lane >> 2, tg = lane & 3;
    int eb = q >> 4, p2 = q & 15;
    int u = j*8 + g8, i = p2*4 + ks;
    int e0 = eb*8 + tg, e1 = e0 + 4;
    unsigned w0 = cvt_tf32(wgt[((size_t)e0*INTERM + i)*UOUT + u]);
    unsigned w1 = cvt_tf32(wgt[((size_t)e1*INTERM + i)*UOUT + u]);
    *(uint2*)&g_W[(size_t)q*4096 + (size_t)((j*4 + ks)*32 + lane)*2] =
        make_uint2(w0, w1);
}

// ---------------- main fused kernel ----------------
// smem: A[2][16KB] (fragment order) | R[2][128 rows x 256B, XOR-swizzled]
#define SM_A0 0
#define SM_A1 16384
#define SM_R0 32768
#define SM_R1 65536
#define SMEMSZ 98304

__global__ __launch_bounds__(512, 1)
void eib_main(const float* __restrict__ rbf, const unsigned* __restrict__ gw,
              float* __restrict__ out, int ne)
{
    extern __shared__ char sm[];
    const int tid = threadIdx.x;
    const int n0 = blockIdx.x * 128;

    // ---- consumer identity (tid < 256) ----
    const int cw = tid >> 5, cl = tid & 31;
    const int wm = cw >> 2, wn = cw & 3;              // 2 m-halves x 4 n-quads
    const int cg8 = cl >> 2, ctg = cl & 3;
    const int cxr = (cg8 >> 1) & 3;
    float acc[4][4][4];
    #pragma unroll
    for (int a = 0; a < 4; ++a)
        #pragma unroll
        for (int b = 0; b < 4; ++b)
            #pragma unroll
            for (int c = 0; c < 4; ++c) acc[a][b][c] = 0.f;
    uint2 Bc[16], Bn[16];

    // ---- producer identity (tid >= 256) ----
    const int pt  = tid - 256;
    const int row = pt >> 1, eh = pt & 1;
    const int pmt = row >> 4;
    const int pg8 = row & 7, phi = (row >> 3) & 1;
    const int pword = phi + 2*eh;
    const int pxr = (pg8 >> 1) & 3;
    const int rsw = row & 15;
    const int nrc = (n0 + row < ne) ? (n0 + row) : (ne - 1);
    float S2[16][4];

    // R staging: 2048 cp16 over 512 threads, 4 consecutive segs/thread
    const int st_row = tid >> 2, st_s0 = (tid & 3) * 4;
    const int st_n = (n0 + st_row < ne) ? (n0 + st_row) : (ne - 1);
    const int st_sw = st_row & 15;

    // pre-issue R(0)
    {
        char* dst = sm + SM_R0 + st_row*256;
        const float* src = &rbf[(size_t)st_n*1024];
        #pragma unroll
        for (int r = 0; r < 4; ++r) {
            int seg = st_s0 + r;
            cp16(dst + ((seg ^ st_sw) << 4), src + seg*4);
        }
        CP_COMMIT();
    }

    for (int q = 0; q <= 128; ++q) {
        if (q + 1 < 128) {       // issue R(q+1)
            char* dst = sm + (((q+1) & 1) ? SM_R1 : SM_R0) + st_row*256;
            const float* src = &rbf[(size_t)st_n*1024 + ((q+1) & 15)*64];
            #pragma unroll
            for (int r = 0; r < 4; ++r) {
                int seg = st_s0 + r;
                cp16(dst + ((seg ^ st_sw) << 4), src + seg*4);
            }
            CP_COMMIT();
        }
        if (q + 1 < 128) CP_WAIT(1); else CP_WAIT(0);
        __syncthreads();   // R(q) + A(q-1) visible

        if (tid < 256) {
            // prefetch B(q) fragments (L2-hot) while doing mma(q-1)
            if (q < 128) {
                const unsigned* bq = gw + (size_t)q*4096;
                #pragma unroll
                for (int nt = 0; nt < 4; ++nt)
                    #pragma unroll
                    for (int ks = 0; ks < 4; ++ks)
                        Bn[nt*4+ks] = *(const uint2*)&bq[
                            (size_t)(((wn*4 + nt)*4 + ks)*32 + cl)*2];
            }
            if (q >= 1) {
                const char* Ab = sm + (((q-1) & 1) ? SM_A1 : SM_A0);
                #pragma unroll
                for (int ks = 0; ks < 4; ++ks) {
                    uint4 af[4];
                    #pragma unroll
                    for (int mt = 0; mt < 4; ++mt)
                        af[mt] = *(const uint4*)(Ab +
                            ((((wm*4 + mt)*4 + ks)*32 + cg8*4 + (ctg ^ cxr)) << 4));
                    #pragma unroll
                    for (int mt = 0; mt < 4; ++mt)
                        #pragma unroll
                        for (int nt = 0; nt < 4; ++nt)
                            MMA(acc[mt][nt], af[mt], Bc[nt*4+ks]);
                }
            }
            #pragma unroll
            for (int j = 0; j < 16; ++j) Bc[j] = Bn[j];
        } else if (q < 128) {
            // -------- producers: A-gen chunk q --------
            if ((q & 15) == 0) {   // reload S slice for new e-block
                int eb = q >> 4;
                const float* sp = &g_S[(size_t)nrc*1024 + eb*8 + eh*4];
                #pragma unroll
                for (int s = 0; s < 16; ++s) {
                    float4 v = *(const float4*)(sp + s*64);
                    S2[s][0] = v.x; S2[s][1] = v.y; S2[s][2] = v.z; S2[s][3] = v.w;
                }
            }
            const char* Rb = sm + ((q & 1) ? SM_R1 : SM_R0) + row*256;
            float pacc[4][4];
            #pragma unroll
            for (int il = 0; il < 4; ++il)
                #pragma unroll
                for (int e = 0; e < 4; ++e) pacc[il][e] = 0.f;
            #pragma unroll
            for (int il = 0; il < 4; ++il)
                #pragma unroll
                for (int sg = 0; sg < 4; ++sg) {
                    int pp = il*4 + sg;
                    float4 rv = *(const float4*)(Rb + ((pp ^ rsw) << 4));
                    float rr[4] = {rv.x, rv.y, rv.z, rv.w};
                    #pragma unroll
                    for (int w = 0; w < 4; ++w) {
                        int s = sg*4 + w;
                        #pragma unroll
                        for (int e = 0; e < 4; ++e)
                            pacc[il][e] += rr[w] * S2[s][e];
                    }
                }
            char* Ab = sm + ((q & 1) ? SM_A1 : SM_A0);
            #pragma unroll
            for (int il = 0; il < 4; ++il)
                #pragma unroll
                for (int e = 0; e < 4; ++e) {
                    int slot = (pmt*4 + il)*32 + pg8*4 + (e ^ pxr);
                    *(unsigned*)(Ab + slot*16 + pword*4) = cvt_tf32(pacc[il][e]);
                }
        }
        // drain reads before next iteration's cp.async reuses sibling slots
        __syncthreads();
    }

    // -------- epilogue: consumers store acc --------
    if (tid < 256) {
        #pragma unroll
        for (int mt = 0; mt < 4; ++mt)
            #pragma unroll
            for (int nt = 0; nt < 4; ++nt) {
                int r0 = wm*64 + mt*16 + cg8;
                int u0 = wn*32 + nt*8 + ctg*2;
                if (n0 + r0 < ne)
                    *(float2*)&out[(size_t)(n0 + r0)*UOUT + u0] =
                        make_float2(acc[mt][nt][0], acc[mt][nt][1]);
                if (n0 + r0 + 8 < ne)
                    *(float2*)&out[(size_t)(n0 + r0 + 8)*UOUT + u0] =
                        make_float2(acc[mt][nt][2], acc[mt][nt][3]);
            }
    }
}

extern "C" void kernel_launch(void* const* d_in, const int* in_sizes, int n_in,
                              void* d_out, int out_size)
{
    const float* rbf = (const float*)d_in[0];
    const float* sph = (const float*)d_in[1];
    const float* m   = (const float*)d_in[2];
    const float* wgt = (const float*)d_in[3];
    const void*  idr = d_in[4];
    const void*  kid = d_in[5];
    int ne = in_sizes[0] / (INTERM * NSPH);
    int nt = in_sizes[4];

    detect_idx_dtype<<<1, 32>>>((const int*)kid, nt);
    init_map<<<(ne*KMAXC + 255)/256, 256>>>(ne);
    scatter_map<<<(nt + 255)/256, 256>>>(idr, kid, nt, ne);
    s_gen<<<(ne + 7)/8, 256>>>(sph, m, ne);
    wstage<<<1024, 256>>>(wgt);

    cudaFuncSetAttribute(eib_main, cudaFuncAttributeMaxDynamicSharedMemorySize, SMEMSZ);
    unsigned* gw;
    cudaGetSymbolAddress((void**)&gw, g_W);
    eib_main<<<(ne + 127)/128, 512, SMEMSZ>>>(rbf, gw, (float*)d_out, ne);
}

// round 15
// speedup vs baseline: 3.3387x; 3.3387x over previous
#include <cuda_runtime.h>
#include <cstdint>

// EfficientInteractionBilinear — fused mma.sync (tf32), K32 chunks, smem-B,
// single-barrier pipeline. Buffers: A x2, R x3, B x4.
// out[n,u] = sum_{i,e} A[n,i,e] * W[e,i,u]
//   S[n,s,e] = sum_k sph[n,s,k]*m2[n,k,e]      (s_gen -> g_S scratch)
//   A[n,c]   = sum_s rbf[n,i,s]*S[n,s,e]       (producer warps, fp32)
//   out      = A @ Wk^T via mma.sync m16n8k8 tf32 (consumer warps)
// K = 4096 = 128 chunks of 32 (chunk q: eb=q>>4 -> 8-e block, p2=q&15 ->
// i-quad; in-chunk k = il*8 + e_local, mma k-slice ks = il).
//
// R14 post-mortem: with ONE barrier/iter the only cross-thread overlap is
// pre-barrier(q+1) cp.async issues (slot q+2) vs body(q) reads. Body reads
// R(q) (dist 2: 3 bufs OK) and B(q-1) (dist 3: 3 bufs COLLIDED -> rel_err
// 0.32). Fix: B is 4-deep. A is safe (bodies of different iterations are
// barrier-separated).

#define NSPH   16
#define KMAXC  16
#define EMB    64
#define INTERM 64
#define UOUT   128
#define MAXE   50176

// ---------------- device scratch (allocations forbidden) ----------------
__device__ int      g_tri[MAXE * KMAXC];
__device__ int      g_idx64;
__device__ float    g_S[(size_t)MAXE * 1024];   // [n][s16][e64]
__device__ unsigned g_W[(size_t)128 * 4096];    // per K32 chunk: B-frag order 16KB

// ---------------- helpers ----------------
__device__ __forceinline__ unsigned cvt_tf32(float f) {
    unsigned r; asm("cvt.rn.tf32.f32 %0, %1;" : "=r"(r) : "f"(f)); return r;
}
__device__ __forceinline__ void cp16(void* smem_dst, const void* gmem_src) {
    unsigned a = (unsigned)__cvta_generic_to_shared(smem_dst);
    asm volatile("cp.async.cg.shared.global [%0], [%1], 16;" :: "r"(a), "l"(gmem_src));
}
#define CP_COMMIT() asm volatile("cp.async.commit_group;" ::: "memory")
#define CP_WAIT(n)  asm volatile("cp.async.wait_group %0;" :: "n"(n) : "memory")

#define MMA(c, a, b) asm volatile( \
    "mma.sync.aligned.m16n8k8.row.col.f32.tf32.tf32.f32 " \
    "{%0,%1,%2,%3}, {%4,%5,%6,%7}, {%8,%9}, {%0,%1,%2,%3};" \
    : "+f"((c)[0]), "+f"((c)[1]), "+f"((c)[2]), "+f"((c)[3]) \
    : "r"((a).x), "r"((a).y), "r"((a).z), "r"((a).w), "r"((b).x), "r"((b).y))

// ---------------- prologue (validated) ----------------
__global__ void detect_idx_dtype(const int* __restrict__ kw, int nt)
{
    if (blockIdx.x == 0 && threadIdx.x == 0) {
        int n = nt < 128 ? nt : 128, f = 1;
        for (int t = 0; t < n; ++t) if (kw[2*t+1] != 0) { f = 0; break; }
        g_idx64 = f;
    }
}
__global__ void init_map(int ne)
{
    int i = blockIdx.x * blockDim.x + threadIdx.x;
    if (i < ne * KMAXC) g_tri[i] = -1;
}
__global__ void scatter_map(const void* idr, const void* kid, int nt, int ne)
{
    int t = blockIdx.x * blockDim.x + threadIdx.x;
    if (t >= nt) return;
    long long e, k;
    if (g_idx64) { e = ((const long long*)idr)[t]; k = ((const long long*)kid)[t]; }
    else         { e = ((const int*)idr)[t];       k = ((const int*)kid)[t]; }
    if (e >= 0 && e < ne && k >= 0 && k < KMAXC) g_tri[(int)e*KMAXC + (int)k] = t;
}

// ---------------- S = sph @ m2, one warp per edge (validated) ----------------
__global__ __launch_bounds__(256) void s_gen(const float* __restrict__ sph,
                                             const float* __restrict__ m, int ne)
{
    __shared__ float sphs[8][256];
    int w = threadIdx.x >> 5, l = threadIdx.x & 31;
    int n = blockIdx.x * 8 + w;
    if (n >= ne) return;
    for (int j = l; j < 256; j += 32) sphs[w][j] = sph[(size_t)n*256 + j];
    int tmine = (l < KMAXC) ? g_tri[n*KMAXC + l] : -1;
    __syncwarp();
    float a0[16], a1[16];
    #pragma unroll
    for (int s = 0; s < 16; ++s) { a0[s] = 0.f; a1[s] = 0.f; }
    for (int k = 0; k < 16; ++k) {
        int t = __shfl_sync(0xFFFFFFFFu, tmine, k);
        float m0 = 0.f, m1 = 0.f;
        if (t >= 0) {
            float2 mv = *(const float2*)&m[(size_t)t*EMB + 2*l];
            m0 = mv.x; m1 = mv.y;
        }
        #pragma unroll
        for (int s = 0; s < 16; ++s) {
            float c = sphs[w][s*16 + k];
            a0[s] += c * m0; a1[s] += c * m1;
        }
    }
    #pragma unroll
    for (int s = 0; s < 16; ++s)
        *(float2*)&g_S[(size_t)n*1024 + s*64 + 2*l] = make_float2(a0[s], a1[s]);
}

// ---------------- W -> tf32 in B-fragment order, K32 chunks (validated R12) --
// chunk q (128): image [j 16][ks 4][lane 32][2 u32] = 16KB
// ks = i_local; b0 = Wk[u=j*8+(lane>>2)][e=eb*8+(lane&3), i=p2*4+ks], b1: e+4
__global__ void wstage(const float* __restrict__ wgt)
{
    int gid = blockIdx.x*256 + threadIdx.x;           // 262144 total
    int lane = gid & 31, ks = (gid >> 5) & 3, j = (gid >> 7) & 15, q = gid >> 11;
    int g8 = lane >> 2, tg = lane & 3;
    int eb = q >> 4, p2 = q & 15;
    int u = j*8 + g8, i = p2*4 + ks;
    int e0 = eb*8 + tg, e1 = e0 + 4;
    unsigned w0 = cvt_tf32(wgt[((size_t)e0*INTERM + i)*UOUT + u]);
    unsigned w1 = cvt_tf32(wgt[((size_t)e1*INTERM + i)*UOUT + u]);
    *(uint2*)&g_W[(size_t)q*4096 + (size_t)((j*4 + ks)*32 + lane)*2] =
        make_uint2(w0, w1);
}

// ---------------- main fused kernel ----------------
// smem: A[2][16KB] | B[4][16KB] | R[3][128 x 256B XOR-swizzled] = 190KB
#define SM_A  0
#define SM_B  32768
#define SM_R  98304
#define SMEMSZ 196608

__global__ __launch_bounds__(512, 1)
void eib_main(const float* __restrict__ rbf, float* __restrict__ out, int ne)
{
    extern __shared__ char sm[];
    const int tid = threadIdx.x;
    const int n0 = blockIdx.x * 128;

    // ---- consumer identity (tid < 256) ----
    const int cw = tid >> 5, cl = tid & 31;
    const int wm = cw >> 2, wn = cw & 3;              // 2 m-halves x 4 n-quads
    const int cg8 = cl >> 2, ctg = cl & 3;
    const int cxr = (cg8 >> 1) & 3;
    float acc[4][4][4];
    #pragma unroll
    for (int a = 0; a < 4; ++a)
        #pragma unroll
        for (int b = 0; b < 4; ++b)
            #pragma unroll
            for (int c = 0; c < 4; ++c) acc[a][b][c] = 0.f;

    // ---- producer identity (tid >= 256) ----
    const int pt  = tid - 256;
    const int row = pt >> 1, eh = pt & 1;
    const int pmt = row >> 4;
    const int pg8 = row & 7, phi = (row >> 3) & 1;
    const int pword = phi + 2*eh;
    const int pxr = (pg8 >> 1) & 3;
    const int rsw = row & 15;
    const int nrc = (n0 + row < ne) ? (n0 + row) : (ne - 1);
    float S2[16][4];

    // R staging: 128 rows x 64 floats; 512 threads x 4 cp16
    const int st_row = tid >> 2, st_s0 = (tid & 3) * 4;
    const int st_n = (n0 + st_row < ne) ? (n0 + st_row) : (ne - 1);
    const int st_sw = st_row & 15;
    const float* st_src = &rbf[(size_t)st_n * 1024];

    // pre-issue R(0) + B(0) as one group
    {
        char* rd = sm + SM_R + 0*32768 + st_row*256;
        #pragma unroll
        for (int r = 0; r < 4; ++r) {
            int seg = st_s0 + r;
            cp16(rd + ((seg ^ st_sw) << 4), st_src + seg*4);
        }
        char* bd = sm + SM_B + 0*16384;
        const char* bs = (const char*)g_W;
        cp16(bd + tid*16, bs + tid*16);
        cp16(bd + (tid + 512)*16, bs + (tid + 512)*16);
        CP_COMMIT();
    }

    for (int q = 0; q <= 128; ++q) {
        if (q + 1 < 128) {   // issue R(q+1) -> slot (q+1)%3, B(q+1) -> slot (q+1)%4
            char* rd = sm + SM_R + ((q + 1) % 3)*32768 + st_row*256;
            const float* src = st_src + ((q + 1) & 15) * 64;
            #pragma unroll
            for (int r = 0; r < 4; ++r) {
                int seg = st_s0 + r;
                cp16(rd + ((seg ^ st_sw) << 4), src + seg*4);
            }
            char* bd = sm + SM_B + ((q + 1) % 4)*16384;
            const char* bs = (const char*)g_W + (size_t)(q + 1)*16384;
            cp16(bd + tid*16, bs + tid*16);
            cp16(bd + (tid + 512)*16, bs + (tid + 512)*16);
            CP_COMMIT();
        }
        if (q + 1 < 128) CP_WAIT(1); else CP_WAIT(0);
        __syncthreads();   // R(q), B(q) arrived; A(q-1) visible

        if (tid < 256) {
            // -------- consumers: mma chunk q-1 --------
            if (q >= 1) {
                const char* Ab = sm + SM_A + ((q - 1) & 1)*16384;
                const char* Bb = sm + SM_B + ((q - 1) % 4)*16384;
                #pragma unroll
                for (int ks = 0; ks < 4; ++ks) {
                    uint4 af[4];
                    #pragma unroll
                    for (int mt = 0; mt < 4; ++mt)
                        af[mt] = *(const uint4*)(Ab +
                            ((((wm*4 + mt)*4 + ks)*32 + cg8*4 + (ctg ^ cxr)) << 4));
                    uint2 bf[4];
                    #pragma unroll
                    for (int nt = 0; nt < 4; ++nt)
                        bf[nt] = *(const uint2*)(Bb +
                            ((((wn*4 + nt)*4 + ks)*32 + cl) << 3));
                    #pragma unroll
                    for (int mt = 0; mt < 4; ++mt)
                        #pragma unroll
                        for (int nt = 0; nt < 4; ++nt)
                            MMA(acc[mt][nt], af[mt], bf[nt]);
                }
            }
        } else if (q < 128) {
            // -------- producers: A-gen chunk q --------
            if ((q & 15) == 0) {   // reload S slice for new e-block
                int eb = q >> 4;
                const float* sp = &g_S[(size_t)nrc*1024 + eb*8 + eh*4];
                #pragma unroll
                for (int s = 0; s < 16; ++s) {
                    float4 v = *(const float4*)(sp + s*64);
                    S2[s][0] = v.x; S2[s][1] = v.y; S2[s][2] = v.z; S2[s][3] = v.w;
                }
            }
            const char* Rb = sm + SM_R + (q % 3)*32768 + row*256;
            float pacc[4][4];
            #pragma unroll
            for (int il = 0; il < 4; ++il)
                #pragma unroll
                for (int e = 0; e < 4; ++e) pacc[il][e] = 0.f;
            #pragma unroll
            for (int il = 0; il < 4; ++il)
                #pragma unroll
                for (int sg = 0; sg < 4; ++sg) {
                    int pp = il*4 + sg;
                    float4 rv = *(const float4*)(Rb + ((pp ^ rsw) << 4));
                    float rr[4] = {rv.x, rv.y, rv.z, rv.w};
                    #pragma unroll
                    for (int w = 0; w < 4; ++w) {
                        int s = sg*4 + w;
                        #pragma unroll
                        for (int e = 0; e < 4; ++e)
                            pacc[il][e] += rr[w] * S2[s][e];
                    }
                }
            char* Ab = sm + SM_A + (q & 1)*16384;
            #pragma unroll
            for (int il = 0; il < 4; ++il)
                #pragma unroll
                for (int e = 0; e < 4; ++e) {
                    int slot = (pmt*4 + il)*32 + pg8*4 + (e ^ pxr);
                    *(unsigned*)(Ab + slot*16 + pword*4) = cvt_tf32(pacc[il][e]);
                }
        }
        // Single barrier per iteration. Overlap window is only
        // pre-barrier(q+1) issues (slot q+2) vs body(q) reads:
        //   R(q): dist 2 over 3 bufs OK; B(q-1): dist 3 over 4 bufs OK.
    }

    // -------- epilogue: consumers store acc --------
    if (tid < 256) {
        #pragma unroll
        for (int mt = 0; mt < 4; ++mt)
            #pragma unroll
            for (int nt = 0; nt < 4; ++nt) {
                int r0 = wm*64 + mt*16 + cg8;
                int u0 = wn*32 + nt*8 + ctg*2;
                if (n0 + r0 < ne)
                    *(float2*)&out[(size_t)(n0 + r0)*UOUT + u0] =
                        make_float2(acc[mt][nt][0], acc[mt][nt][1]);
                if (n0 + r0 + 8 < ne)
                    *(float2*)&out[(size_t)(n0 + r0 + 8)*UOUT + u0] =
                        make_float2(acc[mt][nt][2], acc[mt][nt][3]);
            }
    }
}

extern "C" void kernel_launch(void* const* d_in, const int* in_sizes, int n_in,
                              void* d_out, int out_size)
{
    const float* rbf = (const float*)d_in[0];
    const float* sph = (const float*)d_in[1];
    const float* m   = (const float*)d_in[2];
    const float* wgt = (const float*)d_in[3];
    const void*  idr = d_in[4];
    const void*  kid = d_in[5];
    int ne = in_sizes[0] / (INTERM * NSPH);
    int nt = in_sizes[4];

    detect_idx_dtype<<<1, 32>>>((const int*)kid, nt);
    init_map<<<(ne*KMAXC + 255)/256, 256>>>(ne);
    scatter_map<<<(nt + 255)/256, 256>>>(idr, kid, nt, ne);
    s_gen<<<(ne + 7)/8, 256>>>(sph, m, ne);
    wstage<<<1024, 256>>>(wgt);

    cudaFuncSetAttribute(eib_main, cudaFuncAttributeMaxDynamicSharedMemorySize, SMEMSZ);
    eib_main<<<(ne + 127)/128, 512, SMEMSZ>>>(rbf, (float*)d_out, ne);
}